// round 14
// baseline (speedup 1.0000x reference)
#include <cuda_runtime.h>
#include <cstdint>
#include <cstddef>

// MNIST_RNN: 2-layer LSTM (H=10), T=28, D=28, B=32768, + 10-way linear head.
// R13 = R9 structure (2 elems per thread-pair, gates split across pair,
// f32x2 FMA, anti-LICM volatile LDS, exp/rcp activations — tanh.approx is
// EMULATED on sm_103a and caused the R11 regression) +
//  (1) bias regs folded (kept from R10; benign)
//  (2) row-pair weight staging: 10 LDS.128 issued back-to-back, THEN 40
//      FFMA2s — kills the per-row 20-cyc LDS-latency bubble R9 had.

#define TT 28
#define DD 28
#define HH 10

typedef unsigned long long u64;
typedef unsigned int u32;

__device__ __forceinline__ u32 smem_u32(const void *p) {
    u32 a;
    asm("{ .reg .u64 t; cvta.to.shared.u64 t, %1; cvt.u32.u64 %0, t; }"
        : "=r"(a) : "l"(p));
    return a;
}
__device__ __forceinline__ u64 pack2(float lo, float hi) {
    u64 r;
    asm("mov.b64 %0, {%1, %2};" : "=l"(r) : "f"(lo), "f"(hi));
    return r;
}
__device__ __forceinline__ void unpack2(u64 v, float &lo, float &hi) {
    asm("mov.b64 {%0, %1}, %2;" : "=f"(lo), "=f"(hi) : "l"(v));
}
__device__ __forceinline__ u64 ffma2(u64 a, u64 b, u64 c) {
    u64 d;
    asm("fma.rn.f32x2 %0, %1, %2, %3;" : "=l"(d) : "l"(a), "l"(b), "l"(c));
    return d;
}
// Non-hoistable shared loads (volatile = opaque to LICM/CSE; see R3).
__device__ __forceinline__ void lds_v2u64(u64 &w0, u64 &w1, u32 addr) {
    asm volatile("ld.shared.v2.u64 {%0, %1}, [%2];"
                 : "=l"(w0), "=l"(w1) : "r"(addr));
}
__device__ __forceinline__ float shflx1_f(float v) {
    return __shfl_xor_sync(0xffffffffu, v, 1);
}
__device__ __forceinline__ u64 shflx1_u64(u64 v) {
    u32 lo, hi;
    asm("mov.b64 {%0, %1}, %2;" : "=r"(lo), "=r"(hi) : "l"(v));
    lo = __shfl_xor_sync(0xffffffffu, lo, 1);
    hi = __shfl_xor_sync(0xffffffffu, hi, 1);
    u64 r;
    asm("mov.b64 %0, {%1, %2};" : "=l"(r) : "r"(lo), "r"(hi));
    return r;
}

// exp/rcp-based activations (MUFU.EX2 + MUFU.RCP): ~1e-6 abs error.
// (tanh.approx.f32 is NOT native MUFU on sm_103a — measured regression R11.)
__device__ __forceinline__ float sigf(float x) {
    return __fdividef(1.0f, 1.0f + __expf(-x));
}
__device__ __forceinline__ float tanhf_(float x) {
    return 1.0f - 2.0f * __fdividef(1.0f, 1.0f + __expf(x + x));
}

// smem u64 blob offsets (u64 units). Per-role regions; row = 10 u64 = 80 B.
//  w0x [2][28][10] @0   w0h [2][10][10] @560   w1x @760   w1h @960
//  b0  [2][10]     @1160  b1 [2][10]    @1180
#define U_W0X 0
#define U_W0H 560
#define U_W1X 760
#define U_W1H 960
#define U_B0  1160
#define U_B1  1180
#define U_TOT 1200

// Two input rows at once: 10 staged LDS.128 back-to-back, then 40 FFMA2.
// acc index k = 2*qq + j matches weight word order within a row.
#define ACC2(Wt, r, xa0, xb0, xa1, xb1)                                 \
    {                                                                   \
        u64 _p[10], _q[10];                                             \
        _Pragma("unroll")                                               \
        for (int k = 0; k < 5; k++)                                     \
            lds_v2u64(_p[2 * k], _p[2 * k + 1],                         \
                      (Wt) + ((r) * 5 + k) * 16);                       \
        _Pragma("unroll")                                               \
        for (int k = 0; k < 5; k++)                                     \
            lds_v2u64(_q[2 * k], _q[2 * k + 1],                         \
                      (Wt) + (((r) + 1) * 5 + k) * 16);                 \
        u64 _va0 = pack2((xa0), (xa0)), _vb0 = pack2((xb0), (xb0));     \
        u64 _va1 = pack2((xa1), (xa1)), _vb1 = pack2((xb1), (xb1));     \
        _Pragma("unroll")                                               \
        for (int k = 0; k < 10; k++) {                                  \
            aA[k] = ffma2(_va0, _p[k], aA[k]);                          \
            aB[k] = ffma2(_vb0, _p[k], aB[k]);                          \
        }                                                               \
        _Pragma("unroll")                                               \
        for (int k = 0; k < 10; k++) {                                  \
            aA[k] = ffma2(_va1, _q[k], aA[k]);                          \
            aB[k] = ffma2(_vb1, _q[k], aB[k]);                          \
        }                                                               \
    }

// 10-row (hidden-vector) accumulation = 5 row-pair groups.
#define ACCH2(Wt, hA, hB)                                               \
    ACC2(Wt, 0, hA[0], hB[0], hA[1], hB[1])                             \
    ACC2(Wt, 2, hA[2], hB[2], hA[3], hB[3])                             \
    ACC2(Wt, 4, hA[4], hB[4], hA[5], hB[5])                             \
    ACC2(Wt, 6, hA[6], hB[6], hA[7], hB[7])                             \
    ACC2(Wt, 8, hA[8], hB[8], hA[9], hB[9])

// Exchange accs with partner lane, update MY element's cell state (cv),
// write role-resolved hA/hB arrays for the next accumulation.
// role0: my elem = A, own accs = i,f; partner supplies g,o of A.
// role1: my elem = B, own accs = g,o; partner supplies i,f of B.
#define EXCH_UPDATE(hA, hB, cv)                                         \
    {                                                                   \
        u64 rcv[10];                                                    \
        _Pragma("unroll")                                               \
        for (int k = 0; k < 10; k++) {                                  \
            u64 snd = role ? aA[k] : aB[k];                             \
            rcv[k] = shflx1_u64(snd);                                   \
        }                                                               \
        _Pragma("unroll")                                               \
        for (int jj = 0; jj < 5; jj++) {                                \
            u64 Pi = role ? rcv[jj]     : aA[jj];                       \
            u64 Pf = role ? rcv[5 + jj] : aA[5 + jj];                   \
            u64 Pg = role ? aB[jj]      : rcv[jj];                      \
            u64 Po = role ? aB[5 + jj]  : rcv[5 + jj];                  \
            float i0, i1, f0, f1, g0, g1, o0, o1;                       \
            unpack2(Pi, i0, i1); unpack2(Pf, f0, f1);                   \
            unpack2(Pg, g0, g1); unpack2(Po, o0, o1);                   \
            float cn0 = sigf(f0) * cv[2 * jj]     + sigf(i0) * tanhf_(g0); \
            float cn1 = sigf(f1) * cv[2 * jj + 1] + sigf(i1) * tanhf_(g1); \
            cv[2 * jj] = cn0; cv[2 * jj + 1] = cn1;                     \
            float hm0 = sigf(o0) * tanhf_(cn0);                         \
            float hm1 = sigf(o1) * tanhf_(cn1);                         \
            float ho0 = shflx1_f(hm0);                                  \
            float ho1 = shflx1_f(hm1);                                  \
            hA[2 * jj]     = role ? ho0 : hm0;                          \
            hB[2 * jj]     = role ? hm0 : ho0;                          \
            hA[2 * jj + 1] = role ? ho1 : hm1;                          \
            hB[2 * jj + 1] = role ? hm1 : ho1;                          \
        }                                                               \
    }

__global__ __launch_bounds__(32)
void mnist_rnn_kernel(const float *__restrict__ x,
                      const float *__restrict__ wih0, const float *__restrict__ whh0,
                      const float *__restrict__ bih0, const float *__restrict__ bhh0,
                      const float *__restrict__ wih1, const float *__restrict__ whh1,
                      const float *__restrict__ bih1, const float *__restrict__ bhh1,
                      const float *__restrict__ wcls, const float *__restrict__ bcls,
                      float *__restrict__ out, int B) {
    __shared__ u64 blob[U_TOT];
    __shared__ float swc[100], sbc[10];

    const int tid = threadIdx.x;
    {
        float *f = (float *)blob;
        for (int i = tid; i < 1120; i += 32) {              // w0x
            int r = i / 560, rem = i % 560;
            int d = rem / 20, gg = rem % 20;
            f[i] = wih0[(20 * r + gg) * DD + d];
        }
        for (int i = tid; i < 400; i += 32) {               // w0h/w1x/w1h
            int r = i / 200, rem = i % 200;
            int j = rem / 20, gg = rem % 20;
            f[1120 + i] = whh0[(20 * r + gg) * HH + j];
            f[1520 + i] = wih1[(20 * r + gg) * HH + j];
            f[1920 + i] = whh1[(20 * r + gg) * HH + j];
        }
        for (int i = tid; i < 40; i += 32) {                // biases
            int r = i / 20, gg = i % 20;
            f[2320 + i] = bih0[20 * r + gg] + bhh0[20 * r + gg];
            f[2360 + i] = bih1[20 * r + gg] + bhh1[20 * r + gg];
        }
        for (int i = tid; i < 100; i += 32) swc[i] = wcls[i];
        for (int i = tid; i < 10; i += 32) sbc[i] = bcls[i];
    }
    __syncthreads();

    const u32 sbase = smem_u32(blob);
    const int role = tid & 1;
    const u32 w0x_t = sbase + U_W0X * 8 + role * (28 * 80);
    const u32 w0h_t = sbase + U_W0H * 8 + role * (10 * 80);
    const u32 w1x_t = sbase + U_W1X * 8 + role * (10 * 80);
    const u32 w1h_t = sbase + U_W1H * 8 + role * (10 * 80);
    const u32 sb0_t = sbase + U_B0 * 8 + role * 80;
    const u32 sb1_t = sbase + U_B1 * 8 + role * 80;

    // biases into registers once (outside the t-loop)
    u64 bb0[10], bb1[10];
#pragma unroll
    for (int qq = 0; qq < 5; qq++) {
        lds_v2u64(bb0[2 * qq], bb0[2 * qq + 1], sb0_t + qq * 16);
        lds_v2u64(bb1[2 * qq], bb1[2 * qq + 1], sb1_t + qq * 16);
    }

    const int Bh = B >> 1;
    const int pairIdx = blockIdx.x * 16 + (tid >> 1);
    if (pairIdx >= Bh) return;
    const int bA = pairIdx, bB = pairIdx + Bh;

    const float *xbA = x + (size_t)bA * (TT * DD);
    const float *xbB = x + (size_t)bB * (TT * DD);

    float h0A[HH], h0B[HH], h1A[HH], h1B[HH];   // role-resolved hidden states
    float c0m[HH], c1m[HH];                      // MY element's cell states
#pragma unroll
    for (int j = 0; j < HH; j++) {
        h0A[j] = 0.f; h0B[j] = 0.f; h1A[j] = 0.f; h1B[j] = 0.f;
        c0m[j] = 0.f; c1m[j] = 0.f;
    }

#pragma unroll 1
    for (int t = 0; t < TT; t++) {
        const float4 *xrA = reinterpret_cast<const float4 *>(xbA + t * DD);
        const float4 *xrB = reinterpret_cast<const float4 *>(xbB + t * DD);

        u64 aA[10], aB[10];

        // ---- layer 0: x projection; acc init = bias regs ----
#pragma unroll
        for (int k = 0; k < 10; k++) { aA[k] = bb0[k]; aB[k] = bb0[k]; }
#pragma unroll
        for (int g = 0; g < 7; g++) {
            float4 va = xrA[g], vb = xrB[g];
            ACC2(w0x_t, 4 * g,     va.x, vb.x, va.y, vb.y)
            ACC2(w0x_t, 4 * g + 2, va.z, vb.z, va.w, vb.w)
        }

        // recurrent part of layer 0, then exchange + pointwise update
        ACCH2(w0h_t, h0A, h0B)
        EXCH_UPDATE(h0A, h0B, c0m)

        // ---- layer 1; acc init = bias regs ----
#pragma unroll
        for (int k = 0; k < 10; k++) { aA[k] = bb1[k]; aB[k] = bb1[k]; }
        ACCH2(w1x_t, h0A, h0B)
        ACCH2(w1h_t, h1A, h1B)
        EXCH_UPDATE(h1A, h1B, c1m)
    }

    // classifier head: each thread writes its own element
    const int bm = role ? bB : bA;
#pragma unroll
    for (int k = 0; k < 10; k++) {
        float s = sbc[k];
#pragma unroll
        for (int j = 0; j < HH; j++) {
            float hm = role ? h1B[j] : h1A[j];
            s += hm * swc[k * HH + j];
        }
        out[(size_t)bm * 10 + k] = s;
    }
}

extern "C" void kernel_launch(void *const *d_in, const int *in_sizes, int n_in,
                              void *d_out, int out_size) {
    const float *x    = (const float *)d_in[0];
    const float *wih0 = (const float *)d_in[1];
    const float *whh0 = (const float *)d_in[2];
    const float *bih0 = (const float *)d_in[3];
    const float *bhh0 = (const float *)d_in[4];
    const float *wih1 = (const float *)d_in[5];
    const float *whh1 = (const float *)d_in[6];
    const float *bih1 = (const float *)d_in[7];
    const float *bhh1 = (const float *)d_in[8];
    const float *wcls = (const float *)d_in[9];
    const float *bcls = (const float *)d_in[10];
    float *out = (float *)d_out;

    const int B = in_sizes[0] / (TT * DD);
    const int Bh = B >> 1;
    const int grid = (Bh + 15) / 16;
    mnist_rnn_kernel<<<grid, 32>>>(x, wih0, whh0, bih0, bhh0,
                                   wih1, whh1, bih1, bhh1,
                                   wcls, bcls, out, B);
}

// round 15
// speedup vs baseline: 1.6337x; 1.6337x over previous
#include <cuda_runtime.h>
#include <cstdint>
#include <cstddef>

// MNIST_RNN: 2-layer LSTM (H=10), T=28, D=28, B=32768, + 10-way linear head.
// R14: ONE element per lane-pair, 2-way gate split -> 2048 warps (2x R9's
// 1024; 3.46/SMSP). R9 was latency-bound (issue 41.7%) and both per-warp
// scheduling edits (R11, R13) regressed; this doubles latency hiding and
// turns the kernel LDS-pipe-bound (~192k cyc model ~= 110us). Update is
// parity-split across the pair (each lane does 5 hiddens; partner gate
// scalars via 10 shfl.b32/layer). Volatile LDS weight reads (anti-LICM, R3);
// exp/rcp activations (tanh.approx is emulated on sm_103a, R11).

#define TT 28
#define DD 28
#define HH 10

typedef unsigned long long u64;
typedef unsigned int u32;

__device__ __forceinline__ u32 smem_u32(const void *p) {
    u32 a;
    asm("{ .reg .u64 t; cvta.to.shared.u64 t, %1; cvt.u32.u64 %0, t; }"
        : "=r"(a) : "l"(p));
    return a;
}
__device__ __forceinline__ u64 pack2(float lo, float hi) {
    u64 r;
    asm("mov.b64 %0, {%1, %2};" : "=l"(r) : "f"(lo), "f"(hi));
    return r;
}
__device__ __forceinline__ void unpack2(u64 v, float &lo, float &hi) {
    asm("mov.b64 {%0, %1}, %2;" : "=f"(lo), "=f"(hi) : "l"(v));
}
__device__ __forceinline__ u64 ffma2(u64 a, u64 b, u64 c) {
    u64 d;
    asm("fma.rn.f32x2 %0, %1, %2, %3;" : "=l"(d) : "l"(a), "l"(b), "l"(c));
    return d;
}
// Non-hoistable shared loads (volatile = opaque to LICM/CSE; see R3).
__device__ __forceinline__ void lds_v2u64(u64 &w0, u64 &w1, u32 addr) {
    asm volatile("ld.shared.v2.u64 {%0, %1}, [%2];"
                 : "=l"(w0), "=l"(w1) : "r"(addr));
}
__device__ __forceinline__ float shflx1_f(float v) {
    return __shfl_xor_sync(0xffffffffu, v, 1);
}

// exp/rcp-based activations (MUFU.EX2 + MUFU.RCP): ~1e-6 abs error.
__device__ __forceinline__ float sigf(float x) {
    return __fdividef(1.0f, 1.0f + __expf(-x));
}
__device__ __forceinline__ float tanhf_(float x) {
    return 1.0f - 2.0f * __fdividef(1.0f, 1.0f + __expf(x + x));
}

// smem u64 blob offsets (u64 units). Per-role regions; row = 10 u64 = 80 B.
//  w0x [2][28][10] @0   w0h [2][10][10] @560   w1x @760   w1h @960
//  b0  [2][10]     @1160  b1 [2][10]    @1180
#define U_W0X 0
#define U_W0H 560
#define U_W1X 760
#define U_W1H 960
#define U_B0  1160
#define U_B1  1180
#define U_TOT 1200

// Accumulate one input row into this role's 10 local gate pairs (one elem).
#define ACCROW1(Wt, row, xv)                                            \
    {                                                                   \
        u64 _vx = pack2((xv), (xv));                                    \
        _Pragma("unroll")                                               \
        for (int qq = 0; qq < 5; qq++) {                                \
            u64 _w0, _w1;                                               \
            lds_v2u64(_w0, _w1, (Wt) + ((row) * 5 + qq) * 16);          \
            a[2 * qq]     = ffma2(_vx, _w0, a[2 * qq]);                 \
            a[2 * qq + 1] = ffma2(_vx, _w1, a[2 * qq + 1]);             \
        }                                                               \
    }

#define ACCROW1x4(Wt, base, v4)                                         \
    ACCROW1(Wt, (base) + 0, (v4).x)                                     \
    ACCROW1(Wt, (base) + 1, (v4).y)                                     \
    ACCROW1(Wt, (base) + 2, (v4).z)                                     \
    ACCROW1(Wt, (base) + 3, (v4).w)

#define ACCH1(Wt, hf)                                                   \
    ACCROW1(Wt, 0, hf[0]) ACCROW1(Wt, 1, hf[1])                         \
    ACCROW1(Wt, 2, hf[2]) ACCROW1(Wt, 3, hf[3])                         \
    ACCROW1(Wt, 4, hf[4]) ACCROW1(Wt, 5, hf[5])                         \
    ACCROW1(Wt, 6, hf[6]) ACCROW1(Wt, 7, hf[7])                         \
    ACCROW1(Wt, 8, hf[8]) ACCROW1(Wt, 9, hf[9])

#define LOAD_BIAS1(Bt)                                                  \
    {                                                                   \
        _Pragma("unroll")                                               \
        for (int qq = 0; qq < 5; qq++)                                  \
            lds_v2u64(a[2 * qq], a[2 * qq + 1], (Bt) + qq * 16);        \
    }

// Parity-split pointwise update for ONE element across the lane pair.
// role0 owns i,f pairs (local 0-9) and updates EVEN hiddens (lo scalars);
// role1 owns g,o pairs and updates ODD hiddens (hi scalars).
// Exchange: role0 sends hi halves (partner needs i_hi,f_hi); role1 sends lo
// halves (partner needs g_lo,o_lo). 10 shfl.b32 per layer + 5 for h.
#define EXCH_UPDATE1(hf, cv)                                            \
    {                                                                   \
        float rcv[10];                                                  \
        _Pragma("unroll")                                               \
        for (int k = 0; k < 10; k++) {                                  \
            float _lo, _hi;                                             \
            unpack2(a[k], _lo, _hi);                                    \
            float _snd = role ? _lo : _hi;                              \
            rcv[k] = shflx1_f(_snd);                                    \
        }                                                               \
        _Pragma("unroll")                                               \
        for (int jj = 0; jj < 5; jj++) {                                \
            float l0, h0_, l5, h5_;                                     \
            unpack2(a[jj], l0, h0_);                                    \
            unpack2(a[5 + jj], l5, h5_);                                \
            float i_s = role ? rcv[jj]     : l0;                        \
            float f_s = role ? rcv[5 + jj] : l5;                        \
            float g_s = role ? h0_         : rcv[jj];                   \
            float o_s = role ? h5_         : rcv[5 + jj];               \
            float cn = sigf(f_s) * cv[jj] + sigf(i_s) * tanhf_(g_s);    \
            cv[jj] = cn;                                                \
            float hm = sigf(o_s) * tanhf_(cn);                          \
            float ho = shflx1_f(hm);                                    \
            hf[2 * jj]     = role ? ho : hm;                            \
            hf[2 * jj + 1] = role ? hm : ho;                            \
        }                                                               \
    }

__global__ __launch_bounds__(32)
void mnist_rnn_kernel(const float *__restrict__ x,
                      const float *__restrict__ wih0, const float *__restrict__ whh0,
                      const float *__restrict__ bih0, const float *__restrict__ bhh0,
                      const float *__restrict__ wih1, const float *__restrict__ whh1,
                      const float *__restrict__ bih1, const float *__restrict__ bhh1,
                      const float *__restrict__ wcls, const float *__restrict__ bcls,
                      float *__restrict__ out, int B) {
    __shared__ u64 blob[U_TOT];
    __shared__ float swc[100], sbc[10];

    const int tid = threadIdx.x;
    {
        float *f = (float *)blob;
        for (int i = tid; i < 1120; i += 32) {              // w0x
            int r = i / 560, rem = i % 560;
            int d = rem / 20, gg = rem % 20;
            f[i] = wih0[(20 * r + gg) * DD + d];
        }
        for (int i = tid; i < 400; i += 32) {               // w0h/w1x/w1h
            int r = i / 200, rem = i % 200;
            int j = rem / 20, gg = rem % 20;
            f[1120 + i] = whh0[(20 * r + gg) * HH + j];
            f[1520 + i] = wih1[(20 * r + gg) * HH + j];
            f[1920 + i] = whh1[(20 * r + gg) * HH + j];
        }
        for (int i = tid; i < 40; i += 32) {                // biases
            int r = i / 20, gg = i % 20;
            f[2320 + i] = bih0[20 * r + gg] + bhh0[20 * r + gg];
            f[2360 + i] = bih1[20 * r + gg] + bhh1[20 * r + gg];
        }
        for (int i = tid; i < 100; i += 32) swc[i] = wcls[i];
        for (int i = tid; i < 10; i += 32) sbc[i] = bcls[i];
    }
    __syncthreads();

    const u32 sbase = smem_u32(blob);
    const int role = tid & 1;
    const u32 w0x_t = sbase + U_W0X * 8 + role * (28 * 80);
    const u32 w0h_t = sbase + U_W0H * 8 + role * (10 * 80);
    const u32 w1x_t = sbase + U_W1X * 8 + role * (10 * 80);
    const u32 w1h_t = sbase + U_W1H * 8 + role * (10 * 80);
    const u32 sb0_t = sbase + U_B0 * 8 + role * 80;
    const u32 sb1_t = sbase + U_B1 * 8 + role * 80;

    const int b = blockIdx.x * 16 + (tid >> 1);   // one element per lane-pair
    if (b >= B) return;

    const float *xb = x + (size_t)b * (TT * DD);

    float h0f[HH], h1f[HH];       // full hidden vectors (both parities)
    float c0m[5], c1m[5];         // my-parity cell scalars
#pragma unroll
    for (int j = 0; j < HH; j++) { h0f[j] = 0.f; h1f[j] = 0.f; }
#pragma unroll
    for (int j = 0; j < 5; j++) { c0m[j] = 0.f; c1m[j] = 0.f; }

#pragma unroll 1
    for (int t = 0; t < TT; t++) {
        const float4 *xr = reinterpret_cast<const float4 *>(xb + t * DD);

        u64 a[10];

        // ---- layer 0: x projection (software-pipelined x groups) ----
        LOAD_BIAS1(sb0_t)
        float4 vc = xr[0];
        float4 vn = xr[1];
        ACCROW1x4(w0x_t, 0, vc)
        vc = vn; vn = xr[2];
        ACCROW1x4(w0x_t, 4, vc)
        vc = vn; vn = xr[3];
        ACCROW1x4(w0x_t, 8, vc)
        vc = vn; vn = xr[4];
        ACCROW1x4(w0x_t, 12, vc)
        vc = vn; vn = xr[5];
        ACCROW1x4(w0x_t, 16, vc)
        vc = vn; vn = xr[6];
        ACCROW1x4(w0x_t, 20, vc)
        vc = vn;
        ACCROW1x4(w0x_t, 24, vc)

        // recurrent part of layer 0, then exchange + parity-split update
        ACCH1(w0h_t, h0f)
        EXCH_UPDATE1(h0f, c0m)

        // ---- layer 1 ----
        LOAD_BIAS1(sb1_t)
        ACCH1(w1x_t, h0f)
        ACCH1(w1h_t, h1f)
        EXCH_UPDATE1(h1f, c1m)
    }

    // classifier head: role0 lane writes (both lanes hold identical h1f)
    if (role == 0) {
#pragma unroll
        for (int k = 0; k < 10; k++) {
            float s = sbc[k];
#pragma unroll
            for (int j = 0; j < HH; j++) s += h1f[j] * swc[k * HH + j];
            out[(size_t)b * 10 + k] = s;
        }
    }
}

extern "C" void kernel_launch(void *const *d_in, const int *in_sizes, int n_in,
                              void *d_out, int out_size) {
    const float *x    = (const float *)d_in[0];
    const float *wih0 = (const float *)d_in[1];
    const float *whh0 = (const float *)d_in[2];
    const float *bih0 = (const float *)d_in[3];
    const float *bhh0 = (const float *)d_in[4];
    const float *wih1 = (const float *)d_in[5];
    const float *whh1 = (const float *)d_in[6];
    const float *bih1 = (const float *)d_in[7];
    const float *bhh1 = (const float *)d_in[8];
    const float *wcls = (const float *)d_in[9];
    const float *bcls = (const float *)d_in[10];
    float *out = (float *)d_out;

    const int B = in_sizes[0] / (TT * DD);
    const int grid = (B + 15) / 16;   // 16 elements per 32-thread CTA
    mnist_rnn_kernel<<<grid, 32>>>(x, wih0, whh0, bih0, bhh0,
                                   wih1, whh1, bih1, bhh1,
                                   wcls, bcls, out, B);
}